// round 3
// baseline (speedup 1.0000x reference)
#include <cuda.h>
#include <cuda_runtime.h>
#include <cuda_fp16.h>
#include <cstdint>

// ============================================================================
// Problem dims
// ============================================================================
static constexpr int M_TOTAL = 8192;
static constexpr int N_TOTAL = 16384;
static constexpr int K_TOTAL = 4096;

// GEMM tiling
static constexpr int BM = 128;
static constexpr int BN = 256;
static constexpr int BK = 32;                  // fp16: 64B SMEM rows
static constexpr int STAGES = 8;
static constexpr int K_ITERS = K_TOTAL / BK;   // 128

static constexpr int A_STAGE_BYTES = BM * 64;              // 8192
static constexpr int B_STAGE_BYTES = BN * 64;              // 16384
static constexpr int STAGE_BYTES = A_STAGE_BYTES + B_STAGE_BYTES; // 24576
static constexpr int SMEM_STAGE0 = 1024;                   // after scale array
static constexpr int SMEM_TOTAL = SMEM_STAGE0 + STAGES * STAGE_BYTES; // 197632

// fp16 x, converted once per launch (64 MB static scratch — no runtime alloc)
__device__ __align__(1024) __half g_xh[(size_t)M_TOTAL * K_TOTAL];

// ============================================================================
// Helpers
// ============================================================================
__device__ __forceinline__ uint32_t smem_u32(const void* p) {
    uint32_t a;
    asm("{ .reg .u64 t; cvta.to.shared.u64 t, %1; cvt.u32.u64 %0, t; }"
        : "=r"(a) : "l"(p));
    return a;
}

#define CP_ASYNC_16(dst, src) \
    asm volatile("cp.async.cg.shared.global [%0], [%1], 16;" \
                 :: "r"(dst), "l"(src) : "memory")
#define CP_COMMIT() asm volatile("cp.async.commit_group;" ::: "memory")
#define CP_WAIT_6()  asm volatile("cp.async.wait_group 6;" ::: "memory")

#define LDSM_X4(r0, r1, r2, r3, addr) \
    asm volatile("ldmatrix.sync.aligned.m8n8.x4.shared.b16 {%0,%1,%2,%3}, [%4];" \
                 : "=r"(r0), "=r"(r1), "=r"(r2), "=r"(r3) : "r"(addr))

#define STS128(addr, v0, v1, v2, v3) \
    asm volatile("st.shared.v4.b32 [%0], {%1,%2,%3,%4};" \
                 :: "r"(addr), "r"(v0), "r"(v1), "r"(v2), "r"(v3) : "memory")

#define MMA_16816(d, a, b0, b1)                                               \
    asm volatile(                                                             \
        "mma.sync.aligned.m16n8k16.row.col.f32.f16.f16.f32 "                  \
        "{%0,%1,%2,%3}, {%4,%5,%6,%7}, {%8,%9}, {%0,%1,%2,%3};"               \
        : "+f"((d)[0]), "+f"((d)[1]), "+f"((d)[2]), "+f"((d)[3])              \
        : "r"((a)[0]), "r"((a)[1]), "r"((a)[2]), "r"((a)[3]),                 \
          "r"(b0), "r"(b1))

// ============================================================================
// Prepass: fp32 x -> fp16 g_xh
// ============================================================================
__global__ void convert_x_kernel(const float* __restrict__ x, int n4) {
    int i = blockIdx.x * blockDim.x + threadIdx.x;
    if (i >= n4) return;
    float4 v = reinterpret_cast<const float4*>(x)[i];
    __half2 h0 = __floats2half2_rn(v.x, v.y);
    __half2 h1 = __floats2half2_rn(v.z, v.w);
    uint2 o;
    o.x = *reinterpret_cast<uint32_t*>(&h0);
    o.y = *reinterpret_cast<uint32_t*>(&h1);
    reinterpret_cast<uint2*>(g_xh)[i] = o;
}

// ============================================================================
// GEMM: mma.sync m16n8k16 fp16, cp.async A pipeline, in-kernel bit-unpack B
//   out[M,N] = xh[M,K] @ (sign(bits) * scale[n])^T
//   reference mapping: bit==1 -> +1, bit==0 -> -1 (MSB-first within byte)
// ============================================================================
__global__ void __launch_bounds__(256, 1)
bitlinear_gemm(const int* __restrict__ bp,
               const float* __restrict__ scale,
               float* __restrict__ out) {
    extern __shared__ char smem[];
    const uint32_t sbase = smem_u32(smem);
    const int tid  = threadIdx.x;
    const int wid  = tid >> 5;
    const int lane = tid & 31;

    // --- supertile rasterization: GROUP_M = 8 (pid_m fastest within group) ---
    const int pid   = blockIdx.x;              // 0..4095
    const int pid_m = ((pid >> 9) << 3) + (pid & 7);   // 0..63
    const int pid_n = (pid & 511) >> 3;                // 0..63
    const int m0 = pid_m * BM;
    const int n0 = pid_n * BN;

    // --- per-CTA scales in SMEM ---
    float* s_scale = reinterpret_cast<float*>(smem);
    s_scale[tid] = scale[n0 + tid];

    // --- warp tile coords: 2 (M) x 4 (N) warps, each 64x64 ---
    const int wm = wid >> 2;       // 0..1
    const int wn = wid & 3;        // 0..3

    // --- precomputed ldmatrix lane addressing ---
    // A: rows = m within tile, 64B rows, chunk swizzle c ^= (row>>1)&3
    const int a_hi = lane >> 4;            // k-half selector (0/1)
    int aOff[4], aSwz[4];
#pragma unroll
    for (int mi = 0; mi < 4; mi++) {
        int row = wm * 64 + mi * 16 + (lane & 15);
        aOff[mi] = row * 64;
        aSwz[mi] = (row >> 1) & 3;
    }
    // B: rows = n within tile
    const int b_hi = (lane >> 3) & 1;      // k-half selector
    int bOff[4], bSwz[4];
#pragma unroll
    for (int nt = 0; nt < 4; nt++) {
        int row = wn * 64 + nt * 16 + ((lane >> 4) << 3) + (lane & 7);
        bOff[nt] = row * 64;
        bSwz[nt] = (row >> 1) & 3;
    }

    // --- A cp.async source/dest lane mapping (2 x 16B chunks per thread) ---
    // chunk id ch in [0,512): row = ch>>2, c = ch&3
    const int chRow0 = tid >> 2,          chC0 = tid & 3;
    const int chRow1 = (tid + 256) >> 2,  chC1 = (tid + 256) & 3;
    const uint32_t aDst0 = chRow0 * 64 + ((chC0 ^ ((chRow0 >> 1) & 3)) << 4);
    const uint32_t aDst1 = chRow1 * 64 + ((chC1 ^ ((chRow1 >> 1) & 3)) << 4);
    const __half* aSrc0 = g_xh + (size_t)(m0 + chRow0) * K_TOTAL + chC0 * 8;
    const __half* aSrc1 = g_xh + (size_t)(m0 + chRow1) * K_TOTAL + chC1 * 8;

    // --- B packed source: one 256-row tile, thread t owns row t ---
    // bp element (int32, 8 bits) index = n*512 + k/8 ; uint4 index = n*128 + it
    const uint4* bSrc = reinterpret_cast<const uint4*>(bp) +
                        ((size_t)(n0 + tid) * 128);
    const uint32_t bDstRow = sbase + SMEM_STAGE0 + A_STAGE_BYTES + tid * 64;
    const int bSwzRow = (tid >> 1) & 3;

    // ------------------------------------------------------------------
    // producer for pipeline stage `it` (k block it*32)
    // ------------------------------------------------------------------
    auto produce = [&](int it) {
        const int cs = it & (STAGES - 1);
        const uint32_t sa = sbase + SMEM_STAGE0 + cs * STAGE_BYTES;
        // A via cp.async (16B each)
        CP_ASYNC_16(sa + aDst0, aSrc0 + it * BK);
        CP_ASYNC_16(sa + aDst1, aSrc1 + it * BK);
        // B: load 32 packed bits, unpack to 32 fp16, store 4x16B.
        // sign = NOT bit (bit==1 -> +1), so unpack from complemented word.
        uint4 q = __ldg(bSrc + it);
        const uint32_t brow = bDstRow + cs * STAGE_BYTES;
#pragma unroll
        for (int j = 0; j < 4; j++) {
            uint32_t t = ~((&q.x)[j]);
            uint32_t p0 = 0x3C003C00u | ((t <<  8) & 0x8000u) | ((t << 25) & 0x80000000u);
            uint32_t p1 = 0x3C003C00u | ((t << 10) & 0x8000u) | ((t << 27) & 0x80000000u);
            uint32_t p2 = 0x3C003C00u | ((t << 12) & 0x8000u) | ((t << 29) & 0x80000000u);
            uint32_t p3 = 0x3C003C00u | ((t << 14) & 0x8000u) | ((t << 31) & 0x80000000u);
            STS128(brow + ((j ^ bSwzRow) << 4), p0, p1, p2, p3);
        }
    };

    // --- accumulators ---
    float acc[4][8][4];
#pragma unroll
    for (int mi = 0; mi < 4; mi++)
#pragma unroll
        for (int ni = 0; ni < 8; ni++)
#pragma unroll
            for (int r = 0; r < 4; r++) acc[mi][ni][r] = 0.f;

    // --- prologue: stages 0..6 ---
#pragma unroll
    for (int it = 0; it < STAGES - 1; it++) {
        produce(it);
        CP_COMMIT();
    }

    // --- main loop ---
    for (int i = 0; i < K_ITERS; i++) {
        CP_WAIT_6();
        __syncthreads();

        if (i + STAGES - 1 < K_ITERS) produce(i + STAGES - 1);
        CP_COMMIT();

        const int cs = i & (STAGES - 1);
        const uint32_t sa = sbase + SMEM_STAGE0 + cs * STAGE_BYTES;
        const uint32_t sb = sa + A_STAGE_BYTES;

#pragma unroll
        for (int ks = 0; ks < 2; ks++) {
            uint32_t a[4][4], b[4][4];
#pragma unroll
            for (int mi = 0; mi < 4; mi++) {
                uint32_t ad = sa + aOff[mi] +
                              ((((ks << 1) | a_hi) ^ aSwz[mi]) << 4);
                LDSM_X4(a[mi][0], a[mi][1], a[mi][2], a[mi][3], ad);
            }
#pragma unroll
            for (int nt = 0; nt < 4; nt++) {
                uint32_t bd = sb + bOff[nt] +
                              ((((ks << 1) | b_hi) ^ bSwz[nt]) << 4);
                LDSM_X4(b[nt][0], b[nt][1], b[nt][2], b[nt][3], bd);
            }
#pragma unroll
            for (int mi = 0; mi < 4; mi++)
#pragma unroll
                for (int nt = 0; nt < 4; nt++) {
                    MMA_16816(acc[mi][2 * nt],     a[mi], b[nt][0], b[nt][1]);
                    MMA_16816(acc[mi][2 * nt + 1], a[mi], b[nt][2], b[nt][3]);
                }
        }
    }

    // --- epilogue: scale by scale[n], fp32 stores ---
    const int g  = lane >> 2;
    const int tg = lane & 3;
    const float* sc = s_scale + wn * 64;
#pragma unroll
    for (int mi = 0; mi < 4; mi++) {
        int row = m0 + wm * 64 + mi * 16 + g;
        float* o0 = out + (size_t)row * N_TOTAL + n0 + wn * 64;
        float* o1 = o0 + (size_t)8 * N_TOTAL;
#pragma unroll
        for (int ni = 0; ni < 8; ni++) {
            int co = ni * 8 + tg * 2;
            float s0 = sc[co], s1 = sc[co + 1];
            float2 v0 = make_float2(acc[mi][ni][0] * s0, acc[mi][ni][1] * s1);
            float2 v1 = make_float2(acc[mi][ni][2] * s0, acc[mi][ni][3] * s1);
            *reinterpret_cast<float2*>(o0 + co) = v0;
            *reinterpret_cast<float2*>(o1 + co) = v1;
        }
    }
}

// ============================================================================
// Host
// ============================================================================
extern "C" void kernel_launch(void* const* d_in, const int* in_sizes, int n_in,
                              void* d_out, int out_size) {
    const float* x     = (const float*)d_in[0];
    const int*   bp    = (const int*)d_in[1];
    const float* scale = (const float*)d_in[2];
    float*       out   = (float*)d_out;

    int n4 = M_TOTAL * K_TOTAL / 4;
    convert_x_kernel<<<(n4 + 255) / 256, 256>>>(x, n4);

    cudaFuncSetAttribute(bitlinear_gemm,
                         cudaFuncAttributeMaxDynamicSharedMemorySize, SMEM_TOTAL);
    const int grid = (M_TOTAL / BM) * (N_TOTAL / BN); // 4096
    bitlinear_gemm<<<grid, 256, SMEM_TOTAL>>>(bp, scale, out);
}

// round 5
// speedup vs baseline: 1.3164x; 1.3164x over previous
#include <cuda.h>
#include <cuda_runtime.h>
#include <cuda_fp16.h>
#include <cstdint>

// ============================================================================
// Problem dims
// ============================================================================
static constexpr int M_TOTAL = 8192;
static constexpr int N_TOTAL = 16384;
static constexpr int K_TOTAL = 4096;

// GEMM tiling
static constexpr int BM = 128;
static constexpr int BN = 128;
static constexpr int BK = 32;                  // fp16: 64B SMEM rows
static constexpr int STAGES = 8;
static constexpr int K_ITERS = K_TOTAL / BK;   // 128

static constexpr int A_STAGE_BYTES = BM * 64;  // 8192
static constexpr int BIT_STAGE_BYTES = BN * 4; // 512 (one u32 of bits per n row)
static constexpr int SMEM_A0    = 1024;                              // after scales
static constexpr int SMEM_BITS0 = SMEM_A0 + STAGES * A_STAGE_BYTES;  // 66560
static constexpr int SMEM_TOTAL = SMEM_BITS0 + STAGES * BIT_STAGE_BYTES; // 70656

// Static scratch (no runtime allocation)
__device__ __align__(1024) __half    g_xh[(size_t)M_TOTAL * K_TOTAL];   // 64 MB
__device__ __align__(1024) uint32_t  g_bt[(size_t)K_ITERS * N_TOTAL];   // 32 MB
// g_bt[it * N_TOTAL + n] = ~( b0 | b1<<8 | b2<<16 | b3<<24 ),
//   bi = low byte of bp[n*512 + it*4 + i]  (each bp int32 holds ONE byte of bits)
//   => bit for k-local kl (0..31) lives at position 8*(kl/8) + 7 - (kl%8).

// ============================================================================
// Helpers
// ============================================================================
__device__ __forceinline__ uint32_t smem_u32(const void* p) {
    uint32_t a;
    asm("{ .reg .u64 t; cvta.to.shared.u64 t, %1; cvt.u32.u64 %0, t; }"
        : "=r"(a) : "l"(p));
    return a;
}

#define CP_ASYNC_16(dst, src) \
    asm volatile("cp.async.cg.shared.global [%0], [%1], 16;" \
                 :: "r"(dst), "l"(src) : "memory")
#define CP_COMMIT() asm volatile("cp.async.commit_group;" ::: "memory")
#define CP_WAIT_6()  asm volatile("cp.async.wait_group 6;" ::: "memory")

#define LDSM_X4(r0, r1, r2, r3, addr) \
    asm volatile("ldmatrix.sync.aligned.m8n8.x4.shared.b16 {%0,%1,%2,%3}, [%4];" \
                 : "=r"(r0), "=r"(r1), "=r"(r2), "=r"(r3) : "r"(addr))

#define MMA_16816(d, a, b0, b1)                                               \
    asm volatile(                                                             \
        "mma.sync.aligned.m16n8k16.row.col.f32.f16.f16.f32 "                  \
        "{%0,%1,%2,%3}, {%4,%5,%6,%7}, {%8,%9}, {%0,%1,%2,%3};"               \
        : "+f"((d)[0]), "+f"((d)[1]), "+f"((d)[2]), "+f"((d)[3])              \
        : "r"((a)[0]), "r"((a)[1]), "r"((a)[2]), "r"((a)[3]),                 \
          "r"(b0), "r"(b1))

// ============================================================================
// Prepass 1: fp32 x -> fp16 g_xh
// ============================================================================
__global__ void convert_x_kernel(const float* __restrict__ x, int n4) {
    int i = blockIdx.x * blockDim.x + threadIdx.x;
    if (i >= n4) return;
    float4 v = reinterpret_cast<const float4*>(x)[i];
    __half2 h0 = __floats2half2_rn(v.x, v.y);
    __half2 h1 = __floats2half2_rn(v.z, v.w);
    uint2 o;
    o.x = *reinterpret_cast<uint32_t*>(&h0);
    o.y = *reinterpret_cast<uint32_t*>(&h1);
    reinterpret_cast<uint2*>(g_xh)[i] = o;
}

// ============================================================================
// Prepass 2: pack 4 byte-valued int32s -> one u32 of 32 k-bits, complement,
// and transpose to [it][n] layout.
//   Input:  bp_u4[n * 128 + it]  (uint4 = 4 int32 = 4 bytes = 32 k-bits)
//   Output: g_bt[it * N_TOTAL + n]
// ============================================================================
__global__ void transpose_bits_kernel(const uint4* __restrict__ bp4) {
    __shared__ uint32_t t[32][33];
    const int bx = blockIdx.x;   // n tile  (N_TOTAL/32 = 512)
    const int by = blockIdx.y;   // it tile (K_ITERS/32 = 4)
    const int lx = threadIdx.x;  // 0..31  -> it within tile (read), n (write)
    const int ly = threadIdx.y;  // 0..7
#pragma unroll
    for (int p = 0; p < 4; p++) {
        int row = ly + p * 8;                 // n within tile
        int n   = bx * 32 + row;
        uint4 q = bp4[(size_t)n * 128 + by * 32 + lx];
        uint32_t w = (q.x & 0xFFu) | ((q.y & 0xFFu) << 8) |
                     ((q.z & 0xFFu) << 16) | (q.w << 24);
        t[row][lx] = ~w;                      // complement: bit==1 -> +1
    }
    __syncthreads();
#pragma unroll
    for (int p = 0; p < 4; p++) {
        int row = ly + p * 8;                 // it within tile
        int it  = by * 32 + row;
        g_bt[(size_t)it * N_TOTAL + bx * 32 + lx] = t[lx][row];
    }
}

// ============================================================================
// GEMM: mma.sync m16n8k16 fp16; cp.async A pipeline; B unpacked from bits
// directly into MMA fragments in registers (no fp16 B tile in SMEM).
//   out[M,N] = xh[M,K] @ W^T,  W[n,k] = (bit ? +1 : -1) * scale[n]
// ============================================================================
__global__ void __launch_bounds__(256, 2)
bitlinear_gemm(const float* __restrict__ scale,
               float* __restrict__ out) {
    extern __shared__ char smem[];
    const uint32_t sbase = smem_u32(smem);
    const int tid  = threadIdx.x;
    const int wid  = tid >> 5;
    const int lane = tid & 31;

    // --- supertile rasterization: GROUP_M = 8 ---
    const int pid   = blockIdx.x;                       // 0..8191
    const int pid_m = ((pid >> 10) << 3) + (pid & 7);   // 0..63
    const int pid_n = (pid & 1023) >> 3;                // 0..127
    const int m0 = pid_m * BM;
    const int n0 = pid_n * BN;

    // --- per-CTA scales in SMEM ---
    float* s_scale = reinterpret_cast<float*>(smem);
    if (tid < 128) s_scale[tid] = scale[n0 + tid];

    // --- warp tile: 2 (M) x 4 (N) warps, each 64m x 32n ---
    const int wm = wid >> 2;       // 0..1
    const int wn = wid & 3;        // 0..3

    // --- A ldmatrix lane addressing (64B rows, chunk swizzle c ^= (row>>1)&3)
    const int a_hi = lane >> 4;
    int aOff[4], aSwz[4];
#pragma unroll
    for (int mi = 0; mi < 4; mi++) {
        int row = wm * 64 + mi * 16 + (lane & 15);
        aOff[mi] = row * 64;
        aSwz[mi] = (row >> 1) & 3;
    }

    // --- B fragment unpack constants ---
    // lane's n-row = wn*32 + ni*8 + (lane>>2); fragment bits (within 16-k half):
    //   b0: k = kb, kb+1 ; b1: k = kb+8, kb+9 ; kb = (lane&3)*2
    // bit position of k-local kl in packed word: 8*(kl/8) + 7 - (kl%8)
    const int kb  = (lane & 3) * 2;
    const int sh0 = 8 + kb, sh1 = 25 + kb;   // b0: k, k+1
    const int sh2 = kb,     sh3 = 17 + kb;   // b1: k+8, k+9
    const uint32_t bitRowBase = sbase + SMEM_BITS0 + (wn * 32 + (lane >> 2)) * 4;

    // --- A cp.async mapping (2 x 16B chunks per thread; 512 chunks total) ---
    const int chRow0 = tid >> 2,          chC0 = tid & 3;
    const int chRow1 = (tid + 256) >> 2,  chC1 = (tid + 256) & 3;
    const uint32_t aDst0 = chRow0 * 64 + ((chC0 ^ ((chRow0 >> 1) & 3)) << 4);
    const uint32_t aDst1 = chRow1 * 64 + ((chC1 ^ ((chRow1 >> 1) & 3)) << 4);
    const __half* aSrc0 = g_xh + (size_t)(m0 + chRow0) * K_TOTAL + chC0 * 8;
    const __half* aSrc1 = g_xh + (size_t)(m0 + chRow1) * K_TOTAL + chC1 * 8;

    // --- bits cp.async mapping: 128 u32 per stage, 32 threads x 16B ---
    const uint32_t* bitSrc = g_bt + n0 + tid * 4;   // used by tid<32 only

    auto produce = [&](int it) {
        const int cs = it & (STAGES - 1);
        const uint32_t sa = sbase + SMEM_A0 + cs * A_STAGE_BYTES;
        CP_ASYNC_16(sa + aDst0, aSrc0 + it * BK);
        CP_ASYNC_16(sa + aDst1, aSrc1 + it * BK);
        if (tid < 32) {
            CP_ASYNC_16(sbase + SMEM_BITS0 + cs * BIT_STAGE_BYTES + tid * 16,
                        bitSrc + (size_t)it * N_TOTAL);
        }
    };

    // --- accumulators: [mi][ni][4] ---
    float acc[4][4][4];
#pragma unroll
    for (int mi = 0; mi < 4; mi++)
#pragma unroll
        for (int ni = 0; ni < 4; ni++)
#pragma unroll
            for (int r = 0; r < 4; r++) acc[mi][ni][r] = 0.f;

    // --- prologue ---
#pragma unroll
    for (int it = 0; it < STAGES - 1; it++) {
        produce(it);
        CP_COMMIT();
    }

    // --- main loop ---
    for (int i = 0; i < K_ITERS; i++) {
        CP_WAIT_6();
        __syncthreads();

        if (i + STAGES - 1 < K_ITERS) produce(i + STAGES - 1);
        CP_COMMIT();

        const int cs = i & (STAGES - 1);
        const uint32_t sa = sbase + SMEM_A0 + cs * A_STAGE_BYTES;

        // load the 4 bit-words (one per ni sub-block), broadcast LDS
        uint32_t w[4];
#pragma unroll
        for (int ni = 0; ni < 4; ni++) {
            asm volatile("ld.shared.b32 %0, [%1];"
                         : "=r"(w[ni])
                         : "r"(bitRowBase + cs * BIT_STAGE_BYTES + ni * 32));
        }

#pragma unroll
        for (int ks = 0; ks < 2; ks++) {
            uint32_t a[4][4];
#pragma unroll
            for (int mi = 0; mi < 4; mi++) {
                uint32_t ad = sa + aOff[mi] +
                              ((((ks << 1) | a_hi) ^ aSwz[mi]) << 4);
                LDSM_X4(a[mi][0], a[mi][1], a[mi][2], a[mi][3], ad);
            }
#pragma unroll
            for (int ni = 0; ni < 4; ni++) {
                const uint32_t t = ks ? (w[ni] >> 16) : w[ni];
                const uint32_t b0 = 0x3C003C00u | ((t << sh0) & 0x8000u)
                                               | ((t << sh1) & 0x80000000u);
                const uint32_t b1 = 0x3C003C00u | ((t << sh2) & 0x8000u)
                                               | ((t << sh3) & 0x80000000u);
#pragma unroll
                for (int mi = 0; mi < 4; mi++)
                    MMA_16816(acc[mi][ni], a[mi], b0, b1);
            }
        }
    }

    // --- epilogue: scale by scale[n], fp32 stores ---
    const int g  = lane >> 2;
    const int tg = lane & 3;
    const float* sc = s_scale + wn * 32;
#pragma unroll
    for (int mi = 0; mi < 4; mi++) {
        int row = m0 + wm * 64 + mi * 16 + g;
        float* o0 = out + (size_t)row * N_TOTAL + n0 + wn * 32;
        float* o1 = o0 + (size_t)8 * N_TOTAL;
#pragma unroll
        for (int ni = 0; ni < 4; ni++) {
            int co = ni * 8 + tg * 2;
            float s0 = sc[co], s1 = sc[co + 1];
            float2 v0 = make_float2(acc[mi][ni][0] * s0, acc[mi][ni][1] * s1);
            float2 v1 = make_float2(acc[mi][ni][2] * s0, acc[mi][ni][3] * s1);
            *reinterpret_cast<float2*>(o0 + co) = v0;
            *reinterpret_cast<float2*>(o1 + co) = v1;
        }
    }
}

// ============================================================================
// Host
// ============================================================================
extern "C" void kernel_launch(void* const* d_in, const int* in_sizes, int n_in,
                              void* d_out, int out_size) {
    const float* x     = (const float*)d_in[0];
    const int*   bp    = (const int*)d_in[1];
    const float* scale = (const float*)d_in[2];
    float*       out   = (float*)d_out;

    int n4 = M_TOTAL * K_TOTAL / 4;
    convert_x_kernel<<<(n4 + 255) / 256, 256>>>(x, n4);

    dim3 tb(32, 8);
    dim3 tg(N_TOTAL / 32, K_ITERS / 32);
    transpose_bits_kernel<<<tg, tb>>>((const uint4*)bp);

    cudaFuncSetAttribute(bitlinear_gemm,
                         cudaFuncAttributeMaxDynamicSharedMemorySize, SMEM_TOTAL);
    const int grid = (M_TOTAL / BM) * (N_TOTAL / BN); // 8192
    bitlinear_gemm<<<grid, 256, SMEM_TOTAL>>>(scale, out);
}

// round 6
// speedup vs baseline: 1.3489x; 1.0247x over previous
#include <cuda.h>
#include <cuda_runtime.h>
#include <cuda_fp16.h>
#include <cstdint>

// ============================================================================
// Problem dims
// ============================================================================
static constexpr int M_TOTAL = 8192;
static constexpr int N_TOTAL = 16384;
static constexpr int K_TOTAL = 4096;

// GEMM tiling
static constexpr int BM = 128;
static constexpr int BN = 128;
static constexpr int BK = 64;                  // fp16: 128B SMEM rows
static constexpr int STAGES = 4;
static constexpr int K_ITERS = K_TOTAL / BK;   // 64

static constexpr int A_STAGE_BYTES = BM * 128;   // 16384
static constexpr int BIT_STAGE_BYTES = BN * 8;   // 1024 (two u32 of bits per n row)
static constexpr int SMEM_A0    = 1024;                              // after scales
static constexpr int SMEM_BITS0 = SMEM_A0 + STAGES * A_STAGE_BYTES;  // 66560
static constexpr int SMEM_TOTAL = SMEM_BITS0 + STAGES * BIT_STAGE_BYTES; // 70656

// Static scratch (no runtime allocation)
__device__ __align__(1024) __half    g_xh[(size_t)M_TOTAL * K_TOTAL];       // 64 MB
__device__ __align__(1024) uint32_t  g_bt[(size_t)(K_TOTAL / 32) * N_TOTAL]; // 32 MB
// Layout: g_bt[(i * N_TOTAL + n) * 2 + j] = ~word(n, 2*i + j)   for BK=64 iter i
//   word(n, it) = b0|b1<<8|b2<<16|b3<<24, bi = low byte of bp[n*512 + it*4 + i]
//   bit of k-local kl (0..31) at position 8*(kl/8) + 7 - (kl%8); complement
//   pre-applied so sign bit == packed bit==0 (bit==1 -> +1).

// ============================================================================
// Helpers
// ============================================================================
__device__ __forceinline__ uint32_t smem_u32(const void* p) {
    uint32_t a;
    asm("{ .reg .u64 t; cvta.to.shared.u64 t, %1; cvt.u32.u64 %0, t; }"
        : "=r"(a) : "l"(p));
    return a;
}

#define CP_ASYNC_16(dst, src) \
    asm volatile("cp.async.cg.shared.global [%0], [%1], 16;" \
                 :: "r"(dst), "l"(src) : "memory")
#define CP_COMMIT() asm volatile("cp.async.commit_group;" ::: "memory")
#define CP_WAIT_2()  asm volatile("cp.async.wait_group 2;" ::: "memory")

#define LDSM_X4(r0, r1, r2, r3, addr) \
    asm volatile("ldmatrix.sync.aligned.m8n8.x4.shared.b16 {%0,%1,%2,%3}, [%4];" \
                 : "=r"(r0), "=r"(r1), "=r"(r2), "=r"(r3) : "r"(addr))

#define MMA_16816(d, a, b0, b1)                                               \
    asm volatile(                                                             \
        "mma.sync.aligned.m16n8k16.row.col.f32.f16.f16.f32 "                  \
        "{%0,%1,%2,%3}, {%4,%5,%6,%7}, {%8,%9}, {%0,%1,%2,%3};"               \
        : "+f"((d)[0]), "+f"((d)[1]), "+f"((d)[2]), "+f"((d)[3])              \
        : "r"((a)[0]), "r"((a)[1]), "r"((a)[2]), "r"((a)[3]),                 \
          "r"(b0), "r"(b1))

// ============================================================================
// Prepass 1: fp32 x -> fp16 g_xh
// ============================================================================
__global__ void convert_x_kernel(const float* __restrict__ x, int n4) {
    int i = blockIdx.x * blockDim.x + threadIdx.x;
    if (i >= n4) return;
    float4 v = reinterpret_cast<const float4*>(x)[i];
    __half2 h0 = __floats2half2_rn(v.x, v.y);
    __half2 h1 = __floats2half2_rn(v.z, v.w);
    uint2 o;
    o.x = *reinterpret_cast<uint32_t*>(&h0);
    o.y = *reinterpret_cast<uint32_t*>(&h1);
    reinterpret_cast<uint2*>(g_xh)[i] = o;
}

// ============================================================================
// Prepass 2: pack 4 byte-valued int32s -> one u32 of 32 k-bits, complement,
// transpose to [iter][n][2] layout (iter = k/64 GEMM iteration).
//   Input:  bp_u4[n * 128 + it]  (uint4 = 4 int32 = 4 bytes = 32 k-bits)
//   Output: g_bt[((it>>1) * N_TOTAL + n) * 2 + (it&1)]
// ============================================================================
__global__ void transpose_bits_kernel(const uint4* __restrict__ bp4) {
    __shared__ uint32_t t[32][33];
    const int bx = blockIdx.x;   // n tile  (N_TOTAL/32 = 512)
    const int by = blockIdx.y;   // it tile ((K/32)/32 = 4)
    const int lx = threadIdx.x;  // 0..31
    const int ly = threadIdx.y;  // 0..7
#pragma unroll
    for (int p = 0; p < 4; p++) {
        int row = ly + p * 8;                 // n within tile
        int n   = bx * 32 + row;
        uint4 q = bp4[(size_t)n * 128 + by * 32 + lx];
        uint32_t w = (q.x & 0xFFu) | ((q.y & 0xFFu) << 8) |
                     ((q.z & 0xFFu) << 16) | (q.w << 24);
        t[row][lx] = ~w;                      // complement: bit==1 -> +1
    }
    __syncthreads();
#pragma unroll
    for (int p = 0; p < 4; p++) {
        int row = ly + p * 8;                 // it within tile
        int it  = by * 32 + row;
        int n   = bx * 32 + lx;
        g_bt[((size_t)(it >> 1) * N_TOTAL + n) * 2 + (it & 1)] = t[lx][row];
    }
}

// ============================================================================
// GEMM: mma.sync m16n8k16 fp16; cp.async A pipeline (BK=64); B unpacked from
// bits directly into MMA fragments in registers.
//   out[M,N] = xh[M,K] @ W^T,  W[n,k] = (bit ? +1 : -1) * scale[n]
// ============================================================================
__global__ void __launch_bounds__(256, 2)
bitlinear_gemm(const float* __restrict__ scale,
               float* __restrict__ out) {
    extern __shared__ char smem[];
    const uint32_t sbase = smem_u32(smem);
    const int tid  = threadIdx.x;
    const int wid  = tid >> 5;
    const int lane = tid & 31;

    // --- supertile rasterization: GROUP_M = 8 ---
    const int pid   = blockIdx.x;                       // 0..8191
    const int pid_m = ((pid >> 10) << 3) + (pid & 7);   // 0..63
    const int pid_n = (pid & 1023) >> 3;                // 0..127
    const int m0 = pid_m * BM;
    const int n0 = pid_n * BN;

    // --- per-CTA scales in SMEM ---
    float* s_scale = reinterpret_cast<float*>(smem);
    if (tid < 128) s_scale[tid] = scale[n0 + tid];

    // --- warp tile: 2 (M) x 4 (N) warps, each 64m x 32n ---
    const int wm = wid >> 2;       // 0..1
    const int wn = wid & 3;        // 0..3

    // --- A ldmatrix lane addressing (128B rows, chunk swizzle c ^= row&7) ---
    const int a_hi = lane >> 4;    // chunk lsb within ks-block
    int aOff[4], aSwz[4];
#pragma unroll
    for (int mi = 0; mi < 4; mi++) {
        int row = wm * 64 + mi * 16 + (lane & 15);
        aOff[mi] = row * 128;
        aSwz[mi] = row & 7;
    }

    // --- B fragment unpack constants ---
    const int kb  = (lane & 3) * 2;
    const int sh0 = 8 + kb, sh1 = 25 + kb;   // b0: k, k+1
    const int sh2 = kb,     sh3 = 17 + kb;   // b1: k+8, k+9
    const uint32_t bitRowBase = sbase + SMEM_BITS0 + (wn * 32 + (lane >> 2)) * 8;

    // --- A cp.async mapping (4 x 16B chunks/thread; 1024 chunks/stage) ---
    uint32_t aDst[4];
    const __half* aSrc[4];
#pragma unroll
    for (int p = 0; p < 4; p++) {
        int id  = tid + 256 * p;
        int row = id >> 3, c = id & 7;
        aDst[p] = row * 128 + ((c ^ (row & 7)) << 4);
        aSrc[p] = g_xh + (size_t)(m0 + row) * K_TOTAL + c * 8;
    }

    // --- bits cp.async mapping: 256 u32 per stage = 64 x 16B chunks ---
    const uint32_t* bitSrc = g_bt + (size_t)n0 * 2 + tid * 4;  // tid<64 only

    auto produce = [&](int it) {
        const int cs = it & (STAGES - 1);
        const uint32_t sa = sbase + SMEM_A0 + cs * A_STAGE_BYTES;
#pragma unroll
        for (int p = 0; p < 4; p++)
            CP_ASYNC_16(sa + aDst[p], aSrc[p] + it * BK);
        if (tid < 64) {
            CP_ASYNC_16(sbase + SMEM_BITS0 + cs * BIT_STAGE_BYTES + tid * 16,
                        bitSrc + (size_t)it * N_TOTAL * 2);
        }
    };

    // --- accumulators: [mi][ni][4] ---
    float acc[4][4][4];
#pragma unroll
    for (int mi = 0; mi < 4; mi++)
#pragma unroll
        for (int ni = 0; ni < 4; ni++)
#pragma unroll
            for (int r = 0; r < 4; r++) acc[mi][ni][r] = 0.f;

    // --- prologue: 3 stages in flight ---
#pragma unroll
    for (int it = 0; it < STAGES - 1; it++) {
        produce(it);
        CP_COMMIT();
    }

    // --- main loop ---
    for (int i = 0; i < K_ITERS; i++) {
        CP_WAIT_2();
        __syncthreads();

        if (i + STAGES - 1 < K_ITERS) produce(i + STAGES - 1);
        CP_COMMIT();

        const int cs = i & (STAGES - 1);
        const uint32_t sa = sbase + SMEM_A0 + cs * A_STAGE_BYTES;

        // bit words for this iter: 2 per ni (k 0..31, 32..63)
        uint2 w[4];
#pragma unroll
        for (int ni = 0; ni < 4; ni++) {
            asm volatile("ld.shared.v2.b32 {%0,%1}, [%2];"
                         : "=r"(w[ni].x), "=r"(w[ni].y)
                         : "r"(bitRowBase + cs * BIT_STAGE_BYTES + ni * 64));
        }

#pragma unroll
        for (int ks = 0; ks < 4; ks++) {
            uint32_t a[4][4];
#pragma unroll
            for (int mi = 0; mi < 4; mi++) {
                uint32_t ad = sa + aOff[mi] +
                              ((((ks << 1) | a_hi) ^ aSwz[mi]) << 4);
                LDSM_X4(a[mi][0], a[mi][1], a[mi][2], a[mi][3], ad);
            }
#pragma unroll
            for (int ni = 0; ni < 4; ni++) {
                const uint32_t wsel = (ks & 2) ? w[ni].y : w[ni].x;
                const uint32_t t = (ks & 1) ? (wsel >> 16) : wsel;
                const uint32_t b0 = 0x3C003C00u | ((t << sh0) & 0x8000u)
                                               | ((t << sh1) & 0x80000000u);
                const uint32_t b1 = 0x3C003C00u | ((t << sh2) & 0x8000u)
                                               | ((t << sh3) & 0x80000000u);
#pragma unroll
                for (int mi = 0; mi < 4; mi++)
                    MMA_16816(acc[mi][ni], a[mi], b0, b1);
            }
        }
    }

    // --- epilogue: scale by scale[n], fp32 stores ---
    const int g  = lane >> 2;
    const int tg = lane & 3;
    const float* sc = s_scale + wn * 32;
#pragma unroll
    for (int mi = 0; mi < 4; mi++) {
        int row = m0 + wm * 64 + mi * 16 + g;
        float* o0 = out + (size_t)row * N_TOTAL + n0 + wn * 32;
        float* o1 = o0 + (size_t)8 * N_TOTAL;
#pragma unroll
        for (int ni = 0; ni < 4; ni++) {
            int co = ni * 8 + tg * 2;
            float s0 = sc[co], s1 = sc[co + 1];
            float2 v0 = make_float2(acc[mi][ni][0] * s0, acc[mi][ni][1] * s1);
            float2 v1 = make_float2(acc[mi][ni][2] * s0, acc[mi][ni][3] * s1);
            *reinterpret_cast<float2*>(o0 + co) = v0;
            *reinterpret_cast<float2*>(o1 + co) = v1;
        }
    }
}

// ============================================================================
// Host
// ============================================================================
extern "C" void kernel_launch(void* const* d_in, const int* in_sizes, int n_in,
                              void* d_out, int out_size) {
    const float* x     = (const float*)d_in[0];
    const int*   bp    = (const int*)d_in[1];
    const float* scale = (const float*)d_in[2];
    float*       out   = (float*)d_out;

    int n4 = M_TOTAL * K_TOTAL / 4;
    convert_x_kernel<<<(n4 + 255) / 256, 256>>>(x, n4);

    dim3 tb(32, 8);
    dim3 tg(N_TOTAL / 32, (K_TOTAL / 32) / 32);
    transpose_bits_kernel<<<tg, tb>>>((const uint4*)bp);

    cudaFuncSetAttribute(bitlinear_gemm,
                         cudaFuncAttributeMaxDynamicSharedMemorySize, SMEM_TOTAL);
    const int grid = (M_TOTAL / BM) * (N_TOTAL / BN); // 8192
    bitlinear_gemm<<<grid, 256, SMEM_TOTAL>>>(scale, out);
}